// round 8
// baseline (speedup 1.0000x reference)
#include <cuda_runtime.h>
#include <cstdint>

#define BB 64
#define CC 128
#define OO 128
#define HIDDEN 33
#define NK 4
#define HW_ 3136
#define OUTIMG 25690112
#define XP 36                    // smem pitch in words

// padded NHWC s8 x: [b][58][58][128], viewed as u32[b][58][58][32]
__device__ __align__(16) unsigned int g_x8[(size_t)BB * 58 * 58 * 32];
// packed s8 weights: [k][tap][o][c4]
__device__ __align__(16) unsigned int g_w8[NK * 9 * OO * 32];
__device__ float g_pooled[BB * CC];
__device__ float g_a[BB];
__device__ float g_rqp[BB];
__device__ float g_attn[BB];
__device__ float g_awq[NK];
__device__ int   g_k[BB];

__device__ __forceinline__ uint32_t smem_u32(const void* p) {
    uint32_t a;
    asm("{ .reg .u64 t; cvta.to.shared.u64 t, %1; cvt.u32.u64 %0, t; }" : "=r"(a) : "l"(p));
    return a;
}

// ---------------------------------------------------------------------------
// 1) pooled[b][c] = mean over HxW
// ---------------------------------------------------------------------------
__global__ void pool_kernel(const float* __restrict__ x) {
    int bc = blockIdx.x;
    const float4* p = reinterpret_cast<const float4*>(x + (size_t)bc * HW_);
    float s = 0.f;
    for (int i = threadIdx.x; i < HW_ / 4; i += blockDim.x) {
        float4 v = p[i];
        s += (v.x + v.y) + (v.z + v.w);
    }
    for (int o = 16; o > 0; o >>= 1) s += __shfl_down_sync(0xffffffffu, s, o);
    __shared__ float red[4];
    int w = threadIdx.x >> 5, l = threadIdx.x & 31;
    if (l == 0) red[w] = s;
    __syncthreads();
    if (threadIdx.x == 0)
        g_pooled[bc] = ((red[0] + red[1]) + (red[2] + red[3])) * (1.0f / 3136.0f);
}

// ---------------------------------------------------------------------------
// 2) gate (per-batch scalars; STE/grad_scale forward, rounding-order faithful)
// ---------------------------------------------------------------------------
__global__ void gate_kernel(const float* __restrict__ fc1,
                            const float* __restrict__ fc2,
                            const float* __restrict__ fc2b,
                            const float* __restrict__ alpha_a,
                            float* __restrict__ raw_out) {
    int b = threadIdx.x;
    if (b >= BB) return;
    const float* pl = g_pooled + b * CC;
    float raw[NK];
#pragma unroll
    for (int k = 0; k < NK; ++k) raw[k] = fc2b[k];
    for (int j = 0; j < HIDDEN; ++j) {
        float h = 0.f;
        const float* f1 = fc1 + j * CC;
        for (int c = 0; c < CC; ++c) h = fmaf(pl[c], f1[c], h);
        h = fmaxf(h, 0.f);
#pragma unroll
        for (int k = 0; k < NK; ++k) raw[k] = fmaf(h, fc2[k * HIDDEN + j], raw[k]);
    }
    int kb = 0;
    float best = raw[0];
#pragma unroll
    for (int k = 1; k < NK; ++k)
        if (raw[k] > best) { best = raw[k]; kb = k; }
#pragma unroll
    for (int k = 0; k < NK; ++k) raw_out[b * NK + k] = raw[k];

    float z[NK], m = -1e30f;
#pragma unroll
    for (int k = 0; k < NK; ++k) { z[k] = __fdiv_rn(raw[k], 34.0f); m = fmaxf(m, z[k]); }
    float sum = 0.f, ek = 0.f;
#pragma unroll
    for (int k = 0; k < NK; ++k) {
        float e = expf(z[k] - m);
        sum += e;
        if (k == kb) ek = e;
    }
    float s = __fdiv_rn(ek, sum);
    float attn = __fadd_rn(__fsub_rn(1.0f, s), s);
    float Qp = (float)((1 << (kb + 2)) - 1);
    float rqp = __fmul_rn(attn, Qp);
    float ralpha = __fmul_rn(attn, alpha_a[kb]);
    float g = __fdiv_rn(1.0f, sqrtf(__fmul_rn(401408.0f, rqp)));
    float t = __fmul_rn(ralpha, g);
    float a = __fadd_rn(__fsub_rn(ralpha, t), t);
    g_a[b] = a;
    g_rqp[b] = rqp;
    g_attn[b] = attn;
    g_k[b] = kb;
}

// ---------------------------------------------------------------------------
// 3) x -> padded NHWC s8: g_x8[b][prow][pcol][c4]
// ---------------------------------------------------------------------------
__global__ void xform_kernel(const float* __restrict__ x) {
    __shared__ unsigned int s[56 * 33];
    int b = blockIdx.z, prow = blockIdx.y;
    int tid = threadIdx.x;
    unsigned int* dst = g_x8 + ((size_t)(b * 58 + prow) * 58) * 32;
    if (prow == 0 || prow == 57) {
        for (int i = tid; i < 58 * 32; i += 256) dst[i] = 0;
        return;
    }
    int h = prow - 1;
    float a = g_a[b], rqp = g_rqp[b];
    unsigned char* s8 = reinterpret_cast<unsigned char*>(s);
    for (int i = tid; i < 1792; i += 256) {
        int c = i / 14, w4 = i % 14;
        float4 v4 = *reinterpret_cast<const float4*>(
            x + ((size_t)(b * CC + c)) * HW_ + h * 56 + w4 * 4);
        float v;
        v = fminf(fmaxf(__fdiv_rn(v4.x, a), 0.0f), rqp);
        s8[(w4 * 4 + 0) * 132 + c] = (unsigned char)__float2int_rn(v);
        v = fminf(fmaxf(__fdiv_rn(v4.y, a), 0.0f), rqp);
        s8[(w4 * 4 + 1) * 132 + c] = (unsigned char)__float2int_rn(v);
        v = fminf(fmaxf(__fdiv_rn(v4.z, a), 0.0f), rqp);
        s8[(w4 * 4 + 2) * 132 + c] = (unsigned char)__float2int_rn(v);
        v = fminf(fmaxf(__fdiv_rn(v4.w, a), 0.0f), rqp);
        s8[(w4 * 4 + 3) * 132 + c] = (unsigned char)__float2int_rn(v);
    }
    __syncthreads();
    for (int i = tid; i < 58 * 32; i += 256) {
        int pcol = i >> 5, c4 = i & 31;
        unsigned int v = 0;
        if (pcol >= 1 && pcol <= 56) v = s[(pcol - 1) * 33 + c4];
        dst[i] = v;
    }
}

// ---------------------------------------------------------------------------
// 4) w -> packed s8: g_w8[k][tap][o][c4]
// ---------------------------------------------------------------------------
__global__ void wform_kernel(const float* __restrict__ w,
                             const float* __restrict__ alpha_w) {
    int k = blockIdx.y;
    int i = blockIdx.x * blockDim.x + threadIdx.x;
    float Qpw = (float)((1 << (k + 1)) - 1);
    float Qnw = -(float)(1 << (k + 1));
    float g = __fdiv_rn(1.0f, sqrtf(__fmul_rn(589824.0f, Qpw)));
    float aw = alpha_w[k];
    float t = __fmul_rn(aw, g);
    float awq = __fadd_rn(__fsub_rn(aw, t), t);
    if (i == 0) g_awq[k] = awq;
    int o   = i / 288;
    int r   = i % 288;
    int c4  = r / 9;
    int tap = r % 9;
    unsigned int pk = 0;
#pragma unroll
    for (int j = 0; j < 4; ++j) {
        size_t idx = ((size_t)(k * OO + o) * CC + c4 * 4 + j) * 9 + tap;
        float v = __fdiv_rn(w[idx], awq);
        v = fminf(fmaxf(v, Qnw), Qpw);
        int q = __float2int_rn(v);
        pk |= ((unsigned int)q & 0xffu) << (8 * j);
    }
    g_w8[((size_t)(k * 9 + tap) * OO + o) * 32 + c4] = pk;
}

// ---------------------------------------------------------------------------
// 5) conv: within-block hybrid, px-split.
//    Warps 0-3: IMMA, all 128 o, px 0..47   (2 mf x 6 nf x 4 k = 48 IMMA/tap)
//    Warps 4-7: dp4a, all 128 o, px 48..111 (8 o x 8 px per thread)
//    Both consume the SAME staged smem tiles.
// ---------------------------------------------------------------------------
#define XW (112 * XP)
#define WWI (128 * XP)
#define SMEM_BYTES ((2 * XW + 2 * WWI) * 4)   // 69120

__device__ __forceinline__ void imma(int& c0, int& c1, int& c2, int& c3,
                                     unsigned a0, unsigned a1, unsigned a2, unsigned a3,
                                     unsigned b0, unsigned b1) {
    asm volatile("mma.sync.aligned.m16n8k32.row.col.s32.s8.s8.s32 "
                 "{%0,%1,%2,%3}, {%4,%5,%6,%7}, {%8,%9}, {%0,%1,%2,%3};"
                 : "+r"(c0), "+r"(c1), "+r"(c2), "+r"(c3)
                 : "r"(a0), "r"(a1), "r"(a2), "r"(a3), "r"(b0), "r"(b1));
}
__device__ __forceinline__ void cp16(uint32_t daddr, const void* src) {
    asm volatile("cp.async.cg.shared.global [%0], [%1], 16;" :: "r"(daddr), "l"(src) : "memory");
}

__global__ __launch_bounds__(256, 2) void conv_kernel(const float* __restrict__ bias,
                                                      float* __restrict__ out) {
    extern __shared__ __align__(16) unsigned int smem[];
    const uint32_t sbase = smem_u32(smem);
    const int tid = threadIdx.x;
    const int b = blockIdx.y;
    const int h0 = blockIdx.x * 2;
    const int k = g_k[b];
    const int wid = tid >> 5, lane = tid & 31;

    // IMMA mapping (warps 0-3): warp covers o [wid*32, wid*32+32), px 0..47
    const int gid = lane >> 2, tig = lane & 3;
    const int o0w = wid * 32;
    const int a_row = ((lane >> 3) & 1) * 8 + (lane & 7);
    const int a_kh4 = (lane >> 4) * 4;
    const int b_col = lane & 7;
    const int b_kh4 = ((lane >> 3) & 1) * 4;

    // dp4a mapping (warps 4-7): warp covers o [(wid-4)*32, +32), px 48..111
    // thread: o = od0 + 4*i (og stride-1 in o -> conflict-free),
    //         px = 48 + pg + 8*j (pg stride-1 -> conflict-free)
    const int og = lane >> 3, pg = lane & 7;
    const int od0 = (wid - 4) * 32 + og;

    int acc[64];
#pragma unroll
    for (int i = 0; i < 64; ++i) acc[i] = 0;

    const unsigned int* wkp = g_w8 + (size_t)k * 9 * OO * 32;
    const unsigned int* xbp = g_x8 + (size_t)(b * 58 + h0) * 58 * 32;

    auto stage = [&](int tap, int bs) {
        const unsigned int* wsrc = wkp + (size_t)tap * OO * 32;
        const int dh = tap / 3, dw = tap % 3;
        const unsigned int* xsrc = xbp + (size_t)(dh * 58 + dw) * 32;
        const uint32_t swd = sbase + (2 * XW + bs * WWI) * 4;
        const uint32_t sxd = sbase + (bs * XW) * 4;
#pragma unroll
        for (int t = 0; t < 4; ++t) {
            int i = tid + t * 256;                 // 1024 W float4
            int o = i >> 3, j = i & 7;
            cp16(swd + (o * XP + j * 4) * 4, wsrc + o * 32 + j * 4);
        }
#pragma unroll
        for (int t = 0; t < 4; ++t) {
            int i = tid + t * 256;                 // 896 X float4
            if (i < 896) {
                int px = i >> 3, j = i & 7;
                int r = px / 56, w2 = px % 56;
                cp16(sxd + (px * XP + j * 4) * 4, xsrc + (r * 58 + w2) * 32 + j * 4);
            }
        }
    };

    stage(0, 0);
    asm volatile("cp.async.commit_group;" ::: "memory");

    for (int tap = 0; tap < 9; ++tap) {
        const int bs = tap & 1;
        if (tap + 1 < 9) {
            stage(tap + 1, bs ^ 1);
            asm volatile("cp.async.commit_group;" ::: "memory");
            asm volatile("cp.async.wait_group 1;" ::: "memory");
        } else {
            asm volatile("cp.async.wait_group 0;" ::: "memory");
        }
        __syncthreads();

        if (wid < 4) {
            // ---------------- IMMA: 32 o x 48 px ----------------
            const uint32_t sww = sbase + (2 * XW + bs * WWI) * 4;
            const uint32_t sxw = sbase + (bs * XW) * 4;
#pragma unroll
            for (int ks = 0; ks < 4; ++ks) {
                const int kb8 = ks * 8;
                unsigned a[2][4];
#pragma unroll
                for (int mf = 0; mf < 2; ++mf) {
                    uint32_t ad = sww + ((o0w + mf * 16 + a_row) * XP + kb8 + a_kh4) * 4;
                    asm volatile("ldmatrix.sync.aligned.m8n8.x4.b16 {%0,%1,%2,%3}, [%4];"
                                 : "=r"(a[mf][0]), "=r"(a[mf][1]), "=r"(a[mf][2]), "=r"(a[mf][3])
                                 : "r"(ad));
                }
#pragma unroll
                for (int nf = 0; nf < 6; ++nf) {
                    uint32_t bd = sxw + ((nf * 8 + b_col) * XP + kb8 + b_kh4) * 4;
                    unsigned b0, b1;
                    asm volatile("ldmatrix.sync.aligned.m8n8.x2.b16 {%0,%1}, [%2];"
                                 : "=r"(b0), "=r"(b1) : "r"(bd));
#pragma unroll
                    for (int mf = 0; mf < 2; ++mf) {
                        int* ac = acc + (mf * 6 + nf) * 4;
                        imma(ac[0], ac[1], ac[2], ac[3],
                             a[mf][0], a[mf][1], a[mf][2], a[mf][3], b0, b1);
                    }
                }
            }
        } else {
            // ---------------- dp4a: 32 o x 64 px ----------------
            const unsigned int* swc = smem + 2 * XW + bs * WWI;
            const unsigned int* sxc = smem + bs * XW;
#pragma unroll 1
            for (int c4 = 0; c4 < 32; ++c4) {
                int wv[8];
#pragma unroll
                for (int i = 0; i < 8; ++i) wv[i] = (int)swc[(od0 + 4 * i) * XP + c4];
                int xv[8];
#pragma unroll
                for (int j = 0; j < 8; ++j) xv[j] = (int)sxc[(48 + pg + 8 * j) * XP + c4];
#pragma unroll
                for (int i = 0; i < 8; ++i)
#pragma unroll
                    for (int j = 0; j < 8; ++j)
                        acc[i * 8 + j] = __dp4a(wv[i], xv[j], acc[i * 8 + j]);
            }
        }
        __syncthreads();
    }

    const float attn = g_attn[b];
    const float scale = __fmul_rn(attn, __fmul_rn(g_a[b], g_awq[k]));

    if (wid < 4) {
        // IMMA epilogue: px 0..47 all in row h0
#pragma unroll
        for (int mf = 0; mf < 2; ++mf) {
#pragma unroll
            for (int half = 0; half < 2; ++half) {
                int o = o0w + mf * 16 + gid + half * 8;
                float bb = __fmul_rn(attn, bias[k * OO + o]);
                float* po = out + (size_t)(b * OO + o) * HW_ + h0 * 56 + tig * 2;
#pragma unroll
                for (int nf = 0; nf < 6; ++nf) {
                    float2 v;
                    v.x = fmaf(scale, (float)acc[(mf * 6 + nf) * 4 + half * 2 + 0], bb);
                    v.y = fmaf(scale, (float)acc[(mf * 6 + nf) * 4 + half * 2 + 1], bb);
                    *reinterpret_cast<float2*>(po + nf * 8) = v;
                }
            }
        }
    } else {
        // dp4a epilogue: px 48..111 -> (row, col)
#pragma unroll
        for (int i = 0; i < 8; ++i) {
            int o = od0 + 4 * i;
            float bb = __fmul_rn(attn, bias[k * OO + o]);
            float* po = out + (size_t)(b * OO + o) * HW_ + h0 * 56;
#pragma unroll
            for (int j = 0; j < 8; ++j) {
                int px = 48 + pg + 8 * j;          // 48..111
                po[px] = fmaf(scale, (float)acc[i * 8 + j], bb);  // row-major over 2 rows
            }
        }
    }
}

// ---------------------------------------------------------------------------
extern "C" void kernel_launch(void* const* d_in, const int* in_sizes, int n_in,
                              void* d_out, int out_size) {
    const float* x       = (const float*)d_in[0];
    const float* fc1     = (const float*)d_in[1];
    const float* fc2     = (const float*)d_in[2];
    const float* fc2b    = (const float*)d_in[3];
    const float* alpha_w = (const float*)d_in[4];
    const float* alpha_a = (const float*)d_in[5];
    const float* weight  = (const float*)d_in[6];
    const float* bias    = (const float*)d_in[7];
    float* out = (float*)d_out;

    static int done = 0;
    if (!done) {
        cudaFuncSetAttribute(conv_kernel, cudaFuncAttributeMaxDynamicSharedMemorySize,
                             SMEM_BYTES);
        done = 1;
    }

    pool_kernel<<<BB * CC, 128>>>(x);
    gate_kernel<<<1, 64>>>(fc1, fc2, fc2b, alpha_a, out + OUTIMG);
    wform_kernel<<<dim3(144, NK), 256>>>(weight, alpha_w);
    xform_kernel<<<dim3(1, 58, BB), 256>>>(x);
    conv_kernel<<<dim3(28, BB), 256, SMEM_BYTES>>>(bias, out);
}

// round 9
// speedup vs baseline: 1.0682x; 1.0682x over previous
#include <cuda_runtime.h>
#include <cstdint>

#define BB 64
#define CC 128
#define OO 128
#define HIDDEN 33
#define NK 4
#define HW_ 3136
#define OUTIMG 25690112
#define XP 36                    // smem pitch in words

// padded NHWC s8 x: [b][58][58][128], viewed as u32[b][58][58][32]
__device__ __align__(16) unsigned int g_x8[(size_t)BB * 58 * 58 * 32];
// packed s8 weights: [k][tap][o][c4]
__device__ __align__(16) unsigned int g_w8[NK * 9 * OO * 32];
__device__ float g_pooled[BB * CC];
__device__ float g_a[BB];
__device__ float g_rqp[BB];
__device__ float g_attn[BB];
__device__ float g_awq[NK];
__device__ int   g_k[BB];

__device__ __forceinline__ uint32_t smem_u32(const void* p) {
    uint32_t a;
    asm("{ .reg .u64 t; cvta.to.shared.u64 t, %1; cvt.u32.u64 %0, t; }" : "=r"(a) : "l"(p));
    return a;
}

// ---------------------------------------------------------------------------
// 1) pooled[b][c] = mean over HxW
// ---------------------------------------------------------------------------
__global__ void pool_kernel(const float* __restrict__ x) {
    int bc = blockIdx.x;
    const float4* p = reinterpret_cast<const float4*>(x + (size_t)bc * HW_);
    float s = 0.f;
    for (int i = threadIdx.x; i < HW_ / 4; i += blockDim.x) {
        float4 v = p[i];
        s += (v.x + v.y) + (v.z + v.w);
    }
    for (int o = 16; o > 0; o >>= 1) s += __shfl_down_sync(0xffffffffu, s, o);
    __shared__ float red[4];
    int w = threadIdx.x >> 5, l = threadIdx.x & 31;
    if (l == 0) red[w] = s;
    __syncthreads();
    if (threadIdx.x == 0)
        g_pooled[bc] = ((red[0] + red[1]) + (red[2] + red[3])) * (1.0f / 3136.0f);
}

// ---------------------------------------------------------------------------
// 2) gate (per-batch scalars; STE/grad_scale forward, rounding-order faithful)
// ---------------------------------------------------------------------------
__global__ void gate_kernel(const float* __restrict__ fc1,
                            const float* __restrict__ fc2,
                            const float* __restrict__ fc2b,
                            const float* __restrict__ alpha_a,
                            float* __restrict__ raw_out) {
    int b = threadIdx.x;
    if (b >= BB) return;
    const float* pl = g_pooled + b * CC;
    float raw[NK];
#pragma unroll
    for (int k = 0; k < NK; ++k) raw[k] = fc2b[k];
    for (int j = 0; j < HIDDEN; ++j) {
        float h = 0.f;
        const float* f1 = fc1 + j * CC;
        for (int c = 0; c < CC; ++c) h = fmaf(pl[c], f1[c], h);
        h = fmaxf(h, 0.f);
#pragma unroll
        for (int k = 0; k < NK; ++k) raw[k] = fmaf(h, fc2[k * HIDDEN + j], raw[k]);
    }
    int kb = 0;
    float best = raw[0];
#pragma unroll
    for (int k = 1; k < NK; ++k)
        if (raw[k] > best) { best = raw[k]; kb = k; }
#pragma unroll
    for (int k = 0; k < NK; ++k) raw_out[b * NK + k] = raw[k];

    float z[NK], m = -1e30f;
#pragma unroll
    for (int k = 0; k < NK; ++k) { z[k] = __fdiv_rn(raw[k], 34.0f); m = fmaxf(m, z[k]); }
    float sum = 0.f, ek = 0.f;
#pragma unroll
    for (int k = 0; k < NK; ++k) {
        float e = expf(z[k] - m);
        sum += e;
        if (k == kb) ek = e;
    }
    float s = __fdiv_rn(ek, sum);
    float attn = __fadd_rn(__fsub_rn(1.0f, s), s);
    float Qp = (float)((1 << (kb + 2)) - 1);
    float rqp = __fmul_rn(attn, Qp);
    float ralpha = __fmul_rn(attn, alpha_a[kb]);
    float g = __fdiv_rn(1.0f, sqrtf(__fmul_rn(401408.0f, rqp)));
    float t = __fmul_rn(ralpha, g);
    float a = __fadd_rn(__fsub_rn(ralpha, t), t);
    g_a[b] = a;
    g_rqp[b] = rqp;
    g_attn[b] = attn;
    g_k[b] = kb;
}

// ---------------------------------------------------------------------------
// 3) x -> padded NHWC s8: g_x8[b][prow][pcol][c4]
// ---------------------------------------------------------------------------
__global__ void xform_kernel(const float* __restrict__ x) {
    __shared__ unsigned int s[56 * 33];
    int b = blockIdx.z, prow = blockIdx.y;
    int tid = threadIdx.x;
    unsigned int* dst = g_x8 + ((size_t)(b * 58 + prow) * 58) * 32;
    if (prow == 0 || prow == 57) {
        for (int i = tid; i < 58 * 32; i += 256) dst[i] = 0;
        return;
    }
    int h = prow - 1;
    float a = g_a[b], rqp = g_rqp[b];
    unsigned char* s8 = reinterpret_cast<unsigned char*>(s);
    for (int i = tid; i < 1792; i += 256) {
        int c = i / 14, w4 = i % 14;
        float4 v4 = *reinterpret_cast<const float4*>(
            x + ((size_t)(b * CC + c)) * HW_ + h * 56 + w4 * 4);
        float v;
        v = fminf(fmaxf(__fdiv_rn(v4.x, a), 0.0f), rqp);
        s8[(w4 * 4 + 0) * 132 + c] = (unsigned char)__float2int_rn(v);
        v = fminf(fmaxf(__fdiv_rn(v4.y, a), 0.0f), rqp);
        s8[(w4 * 4 + 1) * 132 + c] = (unsigned char)__float2int_rn(v);
        v = fminf(fmaxf(__fdiv_rn(v4.z, a), 0.0f), rqp);
        s8[(w4 * 4 + 2) * 132 + c] = (unsigned char)__float2int_rn(v);
        v = fminf(fmaxf(__fdiv_rn(v4.w, a), 0.0f), rqp);
        s8[(w4 * 4 + 3) * 132 + c] = (unsigned char)__float2int_rn(v);
    }
    __syncthreads();
    for (int i = tid; i < 58 * 32; i += 256) {
        int pcol = i >> 5, c4 = i & 31;
        unsigned int v = 0;
        if (pcol >= 1 && pcol <= 56) v = s[(pcol - 1) * 33 + c4];
        dst[i] = v;
    }
}

// ---------------------------------------------------------------------------
// 4) w -> packed s8: g_w8[k][tap][o][c4]
// ---------------------------------------------------------------------------
__global__ void wform_kernel(const float* __restrict__ w,
                             const float* __restrict__ alpha_w) {
    int k = blockIdx.y;
    int i = blockIdx.x * blockDim.x + threadIdx.x;
    float Qpw = (float)((1 << (k + 1)) - 1);
    float Qnw = -(float)(1 << (k + 1));
    float g = __fdiv_rn(1.0f, sqrtf(__fmul_rn(589824.0f, Qpw)));
    float aw = alpha_w[k];
    float t = __fmul_rn(aw, g);
    float awq = __fadd_rn(__fsub_rn(aw, t), t);
    if (i == 0) g_awq[k] = awq;
    int o   = i / 288;
    int r   = i % 288;
    int c4  = r / 9;
    int tap = r % 9;
    unsigned int pk = 0;
#pragma unroll
    for (int j = 0; j < 4; ++j) {
        size_t idx = ((size_t)(k * OO + o) * CC + c4 * 4 + j) * 9 + tap;
        float v = __fdiv_rn(w[idx], awq);
        v = fminf(fmaxf(v, Qnw), Qpw);
        int q = __float2int_rn(v);
        pk |= ((unsigned int)q & 0xffu) << (8 * j);
    }
    g_w8[((size_t)(k * 9 + tap) * OO + o) * 32 + c4] = pk;
}

// ---------------------------------------------------------------------------
// 5) conv: hybrid, o-split 64/64, persistent X slab + triple-buffered W,
//    ONE __syncthreads per tap.
//    Warps 0-3: IMMA, o 0..63, all 112 px.  Warps 4-7: dp4a, o 64..127.
// ---------------------------------------------------------------------------
#define SLAB_W (232 * XP)               // 4 rows x 58 cols, pitch 36 -> 8352 words
#define WB_W   (128 * XP)               // 4608 words per W buffer
#define SMEM_WORDS (SLAB_W + 3 * WB_W)  // 22176 words = 88704 B
#define SMEM_BYTES (SMEM_WORDS * 4)

__device__ __forceinline__ void imma(int& c0, int& c1, int& c2, int& c3,
                                     unsigned a0, unsigned a1, unsigned a2, unsigned a3,
                                     unsigned b0, unsigned b1) {
    asm volatile("mma.sync.aligned.m16n8k32.row.col.s32.s8.s8.s32 "
                 "{%0,%1,%2,%3}, {%4,%5,%6,%7}, {%8,%9}, {%0,%1,%2,%3};"
                 : "+r"(c0), "+r"(c1), "+r"(c2), "+r"(c3)
                 : "r"(a0), "r"(a1), "r"(a2), "r"(a3), "r"(b0), "r"(b1));
}
__device__ __forceinline__ void cp16(uint32_t daddr, const void* src) {
    asm volatile("cp.async.cg.shared.global [%0], [%1], 16;" :: "r"(daddr), "l"(src) : "memory");
}

__global__ __launch_bounds__(256, 2) void conv_kernel(const float* __restrict__ bias,
                                                      float* __restrict__ out) {
    extern __shared__ __align__(16) unsigned int smem[];
    const uint32_t sbase = smem_u32(smem);
    const int tid = threadIdx.x;
    const int b = blockIdx.y;
    const int h0 = blockIdx.x * 2;
    const int k = g_k[b];
    const int wid = tid >> 5, lane = tid & 31;

    // IMMA mapping (warps 0-3): o0w in {0,32}, px row r = wid>>1
    const int gid = lane >> 2, tig = lane & 3;
    const int o0w = (wid & 1) * 32;
    const int rB  = (wid >> 1) & 1;       // 0: px 0..55, 1: px 56..111
    const int a_row = ((lane >> 3) & 1) * 8 + (lane & 7);
    const int a_kh4 = (lane >> 4) * 4;
    const int b_col = lane & 7;
    const int b_kh4 = ((lane >> 3) & 1) * 4;
    const int p00 = rB * 58 + b_col;      // lane-static slab position part

    // dp4a mapping (warps 4-7): o = od0 + 4i (16 o/warp), px = pg + 8j (112 px)
    const int og = (lane >> 3) & 3, pg = lane & 7;
    const int od0 = 64 + (wid - 4) * 16 + og;
    int posw36[14];
#pragma unroll
    for (int j = 0; j < 14; ++j) {
        int px = pg + 8 * j;
        int r = px / 56, c = px % 56;
        posw36[j] = (r * 58 + c) * XP;
    }

    int acc[56];
#pragma unroll
    for (int i = 0; i < 56; ++i) acc[i] = 0;

    const unsigned int* wkp = g_w8 + (size_t)k * 9 * OO * 32;
    const unsigned int* xbp = g_x8 + (size_t)(b * 58 + h0) * 58 * 32;

    auto stageW = [&](int tap) {
        const unsigned int* wsrc = wkp + (size_t)tap * OO * 32;
        const uint32_t wb = sbase + (SLAB_W + (tap % 3) * WB_W) * 4;
#pragma unroll
        for (int t = 0; t < 4; ++t) {
            int i = tid + t * 256;                 // 1024 chunks
            int o = i >> 3, j = i & 7;
            cp16(wb + (o * XP + j * 4) * 4, wsrc + o * 32 + j * 4);
        }
    };

    // prologue: slab + W0 (group 0), W1 (group 1)
    {
#pragma unroll
        for (int t = 0; t < 8; ++t) {
            int i = tid + t * 256;                 // 1856 chunks
            if (i < 1856)
                cp16(sbase + ((i >> 3) * XP + (i & 7) * 4) * 4, xbp + i * 4);
        }
        stageW(0);
        asm volatile("cp.async.commit_group;" ::: "memory");
        stageW(1);
        asm volatile("cp.async.commit_group;" ::: "memory");
    }

    for (int tap = 0; tap < 9; ++tap) {
        if (tap < 8) {
            asm volatile("cp.async.wait_group 1;" ::: "memory");
        } else {
            asm volatile("cp.async.wait_group 0;" ::: "memory");
        }
        __syncthreads();
        if (tap + 2 < 9) {
            stageW(tap + 2);
            asm volatile("cp.async.commit_group;" ::: "memory");
        }

        const int dh = tap / 3, dw = tap % 3;
        const int dpos = dh * 58 + dw;
        const uint32_t wb = sbase + (SLAB_W + (tap % 3) * WB_W) * 4;

        if (wid < 4) {
            // ---------------- IMMA: 32 o x 112 px ----------------
            const uint32_t bbase = sbase + ((p00 + dpos) * XP + b_kh4) * 4;
#pragma unroll
            for (int ks = 0; ks < 4; ++ks) {
                const int kb8 = ks * 8;
                unsigned a[2][4];
#pragma unroll
                for (int mf = 0; mf < 2; ++mf) {
                    uint32_t ad = wb + ((o0w + mf * 16 + a_row) * XP + kb8 + a_kh4) * 4;
                    asm volatile("ldmatrix.sync.aligned.m8n8.x4.b16 {%0,%1,%2,%3}, [%4];"
                                 : "=r"(a[mf][0]), "=r"(a[mf][1]), "=r"(a[mf][2]), "=r"(a[mf][3])
                                 : "r"(ad));
                }
#pragma unroll
                for (int nf = 0; nf < 7; ++nf) {
                    uint32_t bd = bbase + (nf * 8 * XP + kb8) * 4;
                    unsigned b0, b1;
                    asm volatile("ldmatrix.sync.aligned.m8n8.x2.b16 {%0,%1}, [%2];"
                                 : "=r"(b0), "=r"(b1) : "r"(bd));
#pragma unroll
                    for (int mf = 0; mf < 2; ++mf) {
                        int* ac = acc + (mf * 7 + nf) * 4;
                        imma(ac[0], ac[1], ac[2], ac[3],
                             a[mf][0], a[mf][1], a[mf][2], a[mf][3], b0, b1);
                    }
                }
            }
        } else {
            // ---------------- dp4a: 16 o x 112 px, c4-pair LDS.64 ----------------
            const unsigned int* swc = smem + SLAB_W + (tap % 3) * WB_W;
            const unsigned int* sxc = smem + dpos * XP;
#pragma unroll 1
            for (int c4 = 0; c4 < 32; c4 += 2) {
                uint2 wv[4];
#pragma unroll
                for (int i = 0; i < 4; ++i)
                    wv[i] = *reinterpret_cast<const uint2*>(swc + (od0 + 4 * i) * XP + c4);
                uint2 xv[14];
#pragma unroll
                for (int j = 0; j < 14; ++j)
                    xv[j] = *reinterpret_cast<const uint2*>(sxc + posw36[j] + c4);
#pragma unroll
                for (int i = 0; i < 4; ++i)
#pragma unroll
                    for (int j = 0; j < 14; ++j) {
                        int v = __dp4a((int)wv[i].x, (int)xv[j].x, acc[i * 14 + j]);
                        acc[i * 14 + j] = __dp4a((int)wv[i].y, (int)xv[j].y, v);
                    }
            }
        }
    }

    const float attn = g_attn[b];
    const float scale = __fmul_rn(attn, __fmul_rn(g_a[b], g_awq[k]));

    if (wid < 4) {
        // IMMA epilogue
#pragma unroll
        for (int mf = 0; mf < 2; ++mf) {
#pragma unroll
            for (int half = 0; half < 2; ++half) {
                int o = o0w + mf * 16 + gid + half * 8;
                float bb = __fmul_rn(attn, bias[k * OO + o]);
                float* po = out + (size_t)(b * OO + o) * HW_ + h0 * 56 + rB * 56 + tig * 2;
#pragma unroll
                for (int nf = 0; nf < 7; ++nf) {
                    float2 v;
                    v.x = fmaf(scale, (float)acc[(mf * 7 + nf) * 4 + half * 2 + 0], bb);
                    v.y = fmaf(scale, (float)acc[(mf * 7 + nf) * 4 + half * 2 + 1], bb);
                    *reinterpret_cast<float2*>(po + nf * 8) = v;
                }
            }
        }
    } else {
        // dp4a epilogue
#pragma unroll
        for (int i = 0; i < 4; ++i) {
            int o = od0 + 4 * i;
            float bb = __fmul_rn(attn, bias[k * OO + o]);
            float* po = out + (size_t)(b * OO + o) * HW_ + h0 * 56 + pg;
#pragma unroll
            for (int j = 0; j < 14; ++j)
                po[8 * j] = fmaf(scale, (float)acc[i * 14 + j], bb);
        }
    }
}

// ---------------------------------------------------------------------------
extern "C" void kernel_launch(void* const* d_in, const int* in_sizes, int n_in,
                              void* d_out, int out_size) {
    const float* x       = (const float*)d_in[0];
    const float* fc1     = (const float*)d_in[1];
    const float* fc2     = (const float*)d_in[2];
    const float* fc2b    = (const float*)d_in[3];
    const float* alpha_w = (const float*)d_in[4];
    const float* alpha_a = (const float*)d_in[5];
    const float* weight  = (const float*)d_in[6];
    const float* bias    = (const float*)d_in[7];
    float* out = (float*)d_out;

    static int done = 0;
    if (!done) {
        cudaFuncSetAttribute(conv_kernel, cudaFuncAttributeMaxDynamicSharedMemorySize,
                             SMEM_BYTES);
        done = 1;
    }

    pool_kernel<<<BB * CC, 128>>>(x);
    gate_kernel<<<1, 64>>>(fc1, fc2, fc2b, alpha_a, out + OUTIMG);
    wform_kernel<<<dim3(144, NK), 256>>>(weight, alpha_w);
    xform_kernel<<<dim3(1, 58, BB), 256>>>(x);
    conv_kernel<<<dim3(28, BB), 256, SMEM_BYTES>>>(bias, out);
}